// round 13
// baseline (speedup 1.0000x reference)
#include <cuda_runtime.h>

// SlidingVariance: x (B=32, L=16384, C=1) fp32, w=64.
// out[b,i] = population variance of x[b, i : min(i+w, L)].
//
// CHUNK=8 warp-local prefix scan, 128 threads (4 warps). A warp spans 256
// staged elements; rawP is the within-warp exclusive prefix ((s,q)
// interleaved float2 in shared). For tile offset o (j = o & 255):
//   windowsum(o) = rawP[o+64] - rawP[o] + (j >= 192 ? warpsum[o>>8] : 0)
// (cross iff prefix index j+64 >= 256, i.e. j >= 256-W; j is a multiple of
//  8 and k<8, so the condition is uniform across a thread's 8 outputs).
// 128 threads stage 1024 elements -> 960 outputs/block, 8 outputs/thread.

#define W        64
#define THREADS  128
#define CHUNK    8
#define STAGE    (THREADS * CHUNK)     // 1024
#define OUT_TILE (STAGE - W)           // 960
#define NWARP    (THREADS / 32)        // 4

__global__ __launch_bounds__(THREADS, 12)
void sliding_var_kernel(const float* __restrict__ x,
                        float* __restrict__ out,
                        int L) {
    __shared__ float2 P[STAGE];        // (prefix_s, prefix_q), raw per warp
    __shared__ float  wsA[NWARP];      // per-warp s totals
    __shared__ float  wsQ[NWARP];      // per-warp q totals

    const int b  = blockIdx.y;
    const int t0 = blockIdx.x * OUT_TILE;
    const float* xb = x + (long)b * L;

    const int t    = threadIdx.x;
    const int lane = t & 31;
    const int wid  = t >> 5;

    // ---- Load 8 elements (two float4; zero past L) ----
    const int idx = t0 + CHUNK * t;
    float4 a, c;
    if (idx + 7 < L) {
        const float4* p = reinterpret_cast<const float4*>(xb + idx);
        a = p[0];
        c = p[1];
    } else {
        a.x = (idx + 0 < L) ? xb[idx + 0] : 0.0f;
        a.y = (idx + 1 < L) ? xb[idx + 1] : 0.0f;
        a.z = (idx + 2 < L) ? xb[idx + 2] : 0.0f;
        a.w = (idx + 3 < L) ? xb[idx + 3] : 0.0f;
        c.x = (idx + 4 < L) ? xb[idx + 4] : 0.0f;
        c.y = (idx + 5 < L) ? xb[idx + 5] : 0.0f;
        c.z = (idx + 6 < L) ? xb[idx + 6] : 0.0f;
        c.w = (idx + 7 < L) ? xb[idx + 7] : 0.0f;
    }

    // ---- Local inclusive prefixes ls[k], lq[k] (k = 0..7) ----
    float ls[8], lq[8];
    ls[0] = a.x;         lq[0] = a.x * a.x;
    ls[1] = ls[0] + a.y; lq[1] = fmaf(a.y, a.y, lq[0]);
    ls[2] = ls[1] + a.z; lq[2] = fmaf(a.z, a.z, lq[1]);
    ls[3] = ls[2] + a.w; lq[3] = fmaf(a.w, a.w, lq[2]);
    ls[4] = ls[3] + c.x; lq[4] = fmaf(c.x, c.x, lq[3]);
    ls[5] = ls[4] + c.y; lq[5] = fmaf(c.y, c.y, lq[4]);
    ls[6] = ls[5] + c.z; lq[6] = fmaf(c.z, c.z, lq[5]);
    ls[7] = ls[6] + c.w; lq[7] = fmaf(c.w, c.w, lq[6]);

    // ---- Warp inclusive scan of chunk sums ----
    float scan_s = ls[7], scan_q = lq[7];
    #pragma unroll
    for (int o = 1; o < 32; o <<= 1) {
        float as = __shfl_up_sync(0xFFFFFFFFu, scan_s, o);
        float aq = __shfl_up_sync(0xFFFFFFFFu, scan_q, o);
        if (lane >= o) { scan_s += as; scan_q += aq; }
    }

    // Within-warp exclusive prefixes at element granularity.
    const float Es = scan_s - ls[7];
    const float Eq = scan_q - lq[7];
    {
        float4* dst = reinterpret_cast<float4*>(&P[CHUNK * t]);
        dst[0] = make_float4(Es,          Eq,          Es + ls[0], Eq + lq[0]);
        dst[1] = make_float4(Es + ls[1],  Eq + lq[1],  Es + ls[2], Eq + lq[2]);
        dst[2] = make_float4(Es + ls[3],  Eq + lq[3],  Es + ls[4], Eq + lq[4]);
        dst[3] = make_float4(Es + ls[5],  Eq + lq[5],  Es + ls[6], Eq + lq[6]);
    }
    if (lane == 31) { wsA[wid] = scan_s; wsQ[wid] = scan_q; }
    __syncthreads();

    // ---- Epilogue: 8 outputs per thread (threads 0..119) ----
    if (t < OUT_TILE / CHUNK) {
        const int o = CHUNK * t;           // tile offset, multiple of 8
        const int i = t0 + o;
        if (i < L) {
            const int j = o & 255;
            const int w = o >> 8;
            // Cross iff prefix index j+k+64 >= 256; uniform over k since
            // j is a multiple of 8: condition is j >= 256 - W.
            const float bs = (j >= 256 - W) ? wsA[w] : 0.0f;
            const float bq = (j >= 256 - W) ? wsQ[w] : 0.0f;

            const float4* Pp = reinterpret_cast<const float4*>(&P[o]);
            const float4* Ph = reinterpret_cast<const float4*>(&P[o + W]);
            float sw[8], qw[8];
            #pragma unroll
            for (int k = 0; k < 4; k++) {
                float4 lo = Pp[k];
                float4 hi = Ph[k];
                sw[2 * k + 0] = hi.x - lo.x + bs;
                qw[2 * k + 0] = hi.y - lo.y + bq;
                sw[2 * k + 1] = hi.z - lo.z + bs;
                qw[2 * k + 1] = hi.w - lo.w + bq;
            }

            float4 r0, r1;
            float* ro = reinterpret_cast<float*>(&r0);
            float* r4 = reinterpret_cast<float*>(&r1);
            if (i + 7 + W <= L) {
                const float inv = 1.0f / (float)W;
                #pragma unroll
                for (int k = 0; k < 4; k++) {
                    float m = sw[k] * inv;
                    ro[k] = fmaf(-m, m, qw[k] * inv);
                }
                #pragma unroll
                for (int k = 0; k < 4; k++) {
                    float m = sw[k + 4] * inv;
                    r4[k] = fmaf(-m, m, qw[k + 4] * inv);
                }
            } else {
                #pragma unroll
                for (int k = 0; k < 8; k++) {
                    int n = min(W, L - (i + k));   // i+k < L (L % 8 == 0)
                    float invn = 1.0f / (float)n;
                    float m = sw[k] * invn;
                    float val = fmaf(-m, m, qw[k] * invn);
                    if (k < 4) ro[k] = val; else r4[k - 4] = val;
                }
            }
            float4* op = reinterpret_cast<float4*>(out + (long)b * L + i);
            op[0] = r0;
            op[1] = r1;
        }
    }
}

extern "C" void kernel_launch(void* const* d_in, const int* in_sizes, int n_in,
                              void* d_out, int out_size) {
    const float* x = (const float*)d_in[0];
    float* out = (float*)d_out;

    const int B = 32;
    const int L = 16384;

    dim3 grid((L + OUT_TILE - 1) / OUT_TILE, B);   // (18, 32) = 576 blocks
    sliding_var_kernel<<<grid, THREADS>>>(x, out, L);
}

// round 14
// speedup vs baseline: 1.2947x; 1.2947x over previous
#include <cuda_runtime.h>

// SlidingVariance: x (B=32, L=16384, C=1) fp32, w=64.
// out[b,i] = population variance of x[b, i : min(i+w, L)].
//
// FINAL: CHUNK=4 warp-local prefix scan (best of 13 measured configs).
// Warp spans 128 staged elements; rawP is the within-warp exclusive prefix
// ((s,q) interleaved float2 in shared). For tile offset o (j = o & 127):
//   windowsum(o) = rawP[o+64] - rawP[o] + (j >= 64 ? warpsum[o>>7] : 0)
// 256 threads stage 1024 elements -> 960 outputs/block, 4 outputs/thread.
// 576 blocks, ~31 warps/SM; measured 5.18us kernel (launch-overhead floor).

#define W        64
#define THREADS  256
#define CHUNK    4
#define STAGE    (THREADS * CHUNK)     // 1024
#define OUT_TILE (STAGE - W)           // 960
#define NWARP    (THREADS / 32)        // 8

__global__ __launch_bounds__(THREADS, 8)
void sliding_var_kernel(const float* __restrict__ x,
                        float* __restrict__ out,
                        int L) {
    __shared__ float2 P[STAGE];        // (prefix_s, prefix_q), raw per warp
    __shared__ float  wsA[NWARP];      // per-warp s totals
    __shared__ float  wsQ[NWARP];      // per-warp q totals

    const int b  = blockIdx.y;
    const int t0 = blockIdx.x * OUT_TILE;
    const float* xb = x + (long)b * L;

    const int t    = threadIdx.x;
    const int lane = t & 31;
    const int wid  = t >> 5;

    // ---- Load 4 elements (zero past L) ----
    const int idx = t0 + CHUNK * t;
    float4 v;
    if (idx + 3 < L) {
        v = *reinterpret_cast<const float4*>(xb + idx);
    } else {
        v.x = (idx + 0 < L) ? xb[idx + 0] : 0.0f;
        v.y = (idx + 1 < L) ? xb[idx + 1] : 0.0f;
        v.z = (idx + 2 < L) ? xb[idx + 2] : 0.0f;
        v.w = (idx + 3 < L) ? xb[idx + 3] : 0.0f;
    }

    // ---- Local inclusive prefixes within the chunk ----
    const float s1 = v.x;
    const float s2 = s1 + v.y;
    const float s3 = s2 + v.z;
    const float cs = s3 + v.w;
    const float q1 = v.x * v.x;
    const float q2 = fmaf(v.y, v.y, q1);
    const float q3 = fmaf(v.z, v.z, q2);
    const float cq = fmaf(v.w, v.w, q3);

    // ---- Warp inclusive scan of chunk sums ----
    float scan_s = cs, scan_q = cq;
    #pragma unroll
    for (int o = 1; o < 32; o <<= 1) {
        float as = __shfl_up_sync(0xFFFFFFFFu, scan_s, o);
        float aq = __shfl_up_sync(0xFFFFFFFFu, scan_q, o);
        if (lane >= o) { scan_s += as; scan_q += aq; }
    }

    // Within-warp exclusive prefixes at element granularity.
    const float Es = scan_s - cs;
    const float Eq = scan_q - cq;
    {
        float4 p01 = make_float4(Es,      Eq,      Es + s1, Eq + q1);
        float4 p23 = make_float4(Es + s2, Eq + q2, Es + s3, Eq + q3);
        float4* dst = reinterpret_cast<float4*>(&P[CHUNK * t]);
        dst[0] = p01;
        dst[1] = p23;
    }
    if (lane == 31) { wsA[wid] = scan_s; wsQ[wid] = scan_q; }
    __syncthreads();

    // ---- Epilogue: 4 outputs per thread (threads 0..239) ----
    if (t < OUT_TILE / CHUNK) {
        const int o = CHUNK * t;           // tile offset, multiple of 4
        const int i = t0 + o;
        if (i < L) {
            const int j = o & 127;
            const int w = o >> 7;
            const float bs = (j >= W) ? wsA[w] : 0.0f;
            const float bq = (j >= W) ? wsQ[w] : 0.0f;

            const float4* Pp = reinterpret_cast<const float4*>(&P[o]);
            const float4* Ph = reinterpret_cast<const float4*>(&P[o + W]);
            float4 lo01 = Pp[0], lo23 = Pp[1];
            float4 hi01 = Ph[0], hi23 = Ph[1];

            float sw0 = hi01.x - lo01.x + bs;
            float qw0 = hi01.y - lo01.y + bq;
            float sw1 = hi01.z - lo01.z + bs;
            float qw1 = hi01.w - lo01.w + bq;
            float sw2 = hi23.x - lo23.x + bs;
            float qw2 = hi23.y - lo23.y + bq;
            float sw3 = hi23.z - lo23.z + bs;
            float qw3 = hi23.w - lo23.w + bq;

            float4 res;
            if (i + 3 + W <= L) {
                const float inv = 1.0f / (float)W;
                float m0 = sw0 * inv, m1 = sw1 * inv;
                float m2 = sw2 * inv, m3 = sw3 * inv;
                res.x = fmaf(-m0, m0, qw0 * inv);
                res.y = fmaf(-m1, m1, qw1 * inv);
                res.z = fmaf(-m2, m2, qw2 * inv);
                res.w = fmaf(-m3, m3, qw3 * inv);
            } else {
                float sw[4] = {sw0, sw1, sw2, sw3};
                float qw[4] = {qw0, qw1, qw2, qw3};
                float* ro = reinterpret_cast<float*>(&res);
                #pragma unroll
                for (int k = 0; k < 4; k++) {
                    int n = min(W, L - (i + k));   // i+k < L (L % 4 == 0)
                    float invn = 1.0f / (float)n;
                    float m = sw[k] * invn;
                    ro[k] = fmaf(-m, m, qw[k] * invn);
                }
            }
            *reinterpret_cast<float4*>(out + (long)b * L + i) = res;
        }
    }
}

extern "C" void kernel_launch(void* const* d_in, const int* in_sizes, int n_in,
                              void* d_out, int out_size) {
    const float* x = (const float*)d_in[0];
    float* out = (float*)d_out;

    const int B = 32;
    const int L = 16384;

    dim3 grid((L + OUT_TILE - 1) / OUT_TILE, B);   // (18, 32) = 576 blocks
    sliding_var_kernel<<<grid, THREADS>>>(x, out, L);
}